// round 2
// baseline (speedup 1.0000x reference)
#include <cuda_runtime.h>
#include <cstdint>

// GlobalWorkspace: exact EMA scan + per-step threshold/top-2 + mask scatter.
//
// Pipeline:
//   K1 k_bitpack : read spikes (128MiB), ballot-pack to bits (4MiB),
//                  zero-fill ignite_mask region of d_out (128MiB).
//   K2 k_scan    : bit-exact sequential EMA per neuron (serial chain over T),
//                  store chunk carries every 32 steps + nmda_final.
//   K3 k_topk    : per 32-step chunk, replay EMA from exact carry, exact
//                  top-2 (u64 keys, lower-index tie-break) + raw max vs thr,
//                  write coverage + the two 1.0 entries per ignited row.
//
// Arithmetic note: XLA contracts (0.99*v + 0.01*s) into fma(0.99, v, 0.01*s);
// 0.01*s is exact for s in {0,1}. We replicate with __fmaf_rn so every
// discrete decision (threshold, top-2) bit-matches the reference.

#define EMA_MUL 0.99f
#define EMA_ADD 0.01f
#define WTA     0.85f
#define THR     0.58f

#define MAX_T 8192
#define MAX_N 4096
#define CHUNK 32

// scratch (static __device__ — no allocations allowed)
static __device__ unsigned int g_bits[(size_t)MAX_T * (MAX_N / 32)];      // 4 MiB
static __device__ float        g_carry[(size_t)(MAX_T / CHUNK) * MAX_N];  // 4 MiB

// ---------------------------------------------------------------- K1
__global__ void k_bitpack(const float* __restrict__ spikes,
                          float* __restrict__ out_mask,
                          long long total)
{
    long long stride = (long long)gridDim.x * blockDim.x;
    long long i = (long long)blockIdx.x * blockDim.x + threadIdx.x;
    for (; i < total; i += stride) {
        float s = spikes[i];
        unsigned m = __ballot_sync(0xffffffffu, s != 0.0f);
        if ((threadIdx.x & 31) == 0) g_bits[i >> 5] = m;
        out_mask[i] = 0.0f;
    }
}

// ---------------------------------------------------------------- K2
// 1 thread per neuron. blockDim=128, grid = N/128.
__global__ __launch_bounds__(128) void k_scan(const float* __restrict__ nmda0,
                                              float* __restrict__ nmda_final,
                                              int T, int NW /* = N/32 */)
{
    int n  = blockIdx.x * blockDim.x + threadIdx.x;
    int wq = n >> 5;                 // uniform per warp
    unsigned bitm = 1u << (n & 31);
    int N = NW << 5;

    float v = nmda0[n];

    unsigned wa[CHUNK], wb[CHUNK];
    int nblocks = T / CHUNK;         // 256 (even)

    #pragma unroll
    for (int i = 0; i < CHUNK; i++) wa[i] = g_bits[(size_t)i * NW + wq];

    for (int b = 0; b < nblocks; b += 2) {
        g_carry[(size_t)b * N + n] = v;
        // prefetch block b+1
        {
            int t1 = (b + 1) * CHUNK;
            #pragma unroll
            for (int i = 0; i < CHUNK; i++) wb[i] = g_bits[(size_t)(t1 + i) * NW + wq];
        }
        #pragma unroll
        for (int i = 0; i < CHUNK; i++) {
            float a = (wa[i] & bitm) ? EMA_ADD : 0.0f;
            v = __fmaf_rn(EMA_MUL, v, a);      // bit-exact vs XLA's contracted form
        }
        g_carry[(size_t)(b + 1) * N + n] = v;
        // prefetch block b+2
        if (b + 2 < nblocks) {
            int t2 = (b + 2) * CHUNK;
            #pragma unroll
            for (int i = 0; i < CHUNK; i++) wa[i] = g_bits[(size_t)(t2 + i) * NW + wq];
        }
        #pragma unroll
        for (int i = 0; i < CHUNK; i++) {
            float a = (wb[i] & bitm) ? EMA_ADD : 0.0f;
            v = __fmaf_rn(EMA_MUL, v, a);
        }
    }
    nmda_final[n] = v;
}

// ---------------------------------------------------------------- K3
__device__ __forceinline__ void top2_merge(unsigned long long& m1, unsigned long long& m2,
                                           unsigned long long o1, unsigned long long o2)
{
    bool g = m1 > o1;
    unsigned long long hi = g ? m1 : o1;
    unsigned long long lo = g ? o1 : m1;
    unsigned long long s2 = (m2 > o2) ? m2 : o2;
    m1 = hi;
    m2 = (lo > s2) ? lo : s2;
}

// 256 threads, 16 neurons/thread (N must be 4096). blockIdx = chunk (32 steps).
__global__ __launch_bounds__(256) void k_topk(float* __restrict__ out_mask,
                                              float* __restrict__ out_cov,
                                              int N)
{
    __shared__ unsigned sbits[CHUNK * 128];           // 16 KB bit tile
    __shared__ unsigned long long sm1[CHUNK * 8];
    __shared__ unsigned long long sm2[CHUNK * 8];
    __shared__ float smax[CHUNK * 8];
    __shared__ unsigned sidx[CHUNK * 2];

    const int tid = threadIdx.x;
    const int c   = blockIdx.x;
    const int w   = tid >> 5, lane = tid & 31;
    const int NW  = N >> 5;                           // 128

    // load bit tile (coalesced)
    {
        const unsigned* bp = g_bits + (size_t)c * CHUNK * NW;
        #pragma unroll
        for (int i = 0; i < (CHUNK * 128) / 256; i++)
            sbits[tid + i * 256] = bp[tid + i * 256];
    }

    // load exact carry for my 16 neurons
    const int base = tid * 16;
    float ema[16];
    {
        const float4* cr = (const float4*)(g_carry + (size_t)c * N + base);
        #pragma unroll
        for (int q = 0; q < 4; q++) {
            float4 f = cr[q];
            ema[q * 4 + 0] = f.x; ema[q * 4 + 1] = f.y;
            ema[q * 4 + 2] = f.z; ema[q * 4 + 3] = f.w;
        }
    }
    __syncthreads();

    const unsigned invb = ~(unsigned)base;   // ~ (base + j) = invb - j  (no borrow, idx < 2^12)

    // phase A: replay 32 steps, per-warp top2 + rawmax each step
    for (int t = 0; t < CHUNK; t++) {
        unsigned word = sbits[t * 128 + (tid >> 1)];
        unsigned half = word >> ((tid & 1) << 4);

        #pragma unroll
        for (int j = 0; j < 16; j++) {
            float a = ((half >> j) & 1u) ? EMA_ADD : 0.0f;
            ema[j] = __fmaf_rn(EMA_MUL, ema[j], a);   // identical to K2's update
        }

        float rmx = ema[0];
        #pragma unroll
        for (int j = 1; j < 16; j++) rmx = fmaxf(rmx, ema[j]);

        // keys: (score_bits << 32) | ~idx  — score >= 0 so bits are order-monotone;
        // larger ~idx == smaller idx wins ties (jax top_k stable semantics)
        unsigned long long key[16];
        #pragma unroll
        for (int j = 0; j < 16; j++) {
            unsigned sb = __float_as_uint(__fmul_rn(ema[j], WTA));
            key[j] = ((unsigned long long)sb << 32) | (unsigned long long)(invb - j);
        }

        unsigned long long p1[8], p2[8];
        #pragma unroll
        for (int p = 0; p < 8; p++) {
            unsigned long long ka = key[2 * p], kb = key[2 * p + 1];
            bool g = ka > kb;
            p1[p] = g ? ka : kb;
            p2[p] = g ? kb : ka;
        }
        #pragma unroll
        for (int s = 1; s < 8; s <<= 1)
            #pragma unroll
            for (int p = 0; p < 8; p += 2 * s)
                top2_merge(p1[p], p2[p], p1[p + s], p2[p + s]);

        unsigned long long m1 = p1[0], m2 = p2[0];
        #pragma unroll
        for (int d = 16; d >= 1; d >>= 1) {
            unsigned long long o1 = __shfl_xor_sync(0xffffffffu, m1, d);
            unsigned long long o2 = __shfl_xor_sync(0xffffffffu, m2, d);
            float om            = __shfl_xor_sync(0xffffffffu, rmx, d);
            top2_merge(m1, m2, o1, o2);
            rmx = fmaxf(rmx, om);
        }
        if (lane == 0) { sm1[t * 8 + w] = m1; sm2[t * 8 + w] = m2; smax[t * 8 + w] = rmx; }
    }
    __syncthreads();

    // phase B: cross-warp reduce (8 entries per step), finalize per step
    const float covval = __fdiv_rn(2.0f, (float)N);
    for (int t = w; t < CHUNK; t += 8) {
        unsigned long long m1 = 0ull, m2 = 0ull;
        float rmx = 0.0f;
        if (lane < 8) { m1 = sm1[t * 8 + lane]; m2 = sm2[t * 8 + lane]; rmx = smax[t * 8 + lane]; }
        #pragma unroll
        for (int d = 4; d >= 1; d >>= 1) {
            unsigned long long o1 = __shfl_xor_sync(0xffffffffu, m1, d);
            unsigned long long o2 = __shfl_xor_sync(0xffffffffu, m2, d);
            float om            = __shfl_xor_sync(0xffffffffu, rmx, d);
            top2_merge(m1, m2, o1, o2);
            rmx = fmaxf(rmx, om);
        }
        if (lane == 0) {
            bool ign = (rmx >= THR);
            int tg = c * CHUNK + t;
            out_cov[tg] = ign ? covval : 0.0f;
            sidx[t * 2 + 0] = ign ? ~(unsigned)(m1 & 0xffffffffull) : 0xffffffffu;
            sidx[t * 2 + 1] = ign ? ~(unsigned)(m2 & 0xffffffffull) : 0xffffffffu;
        }
    }
    __syncthreads();

    // phase D: scatter the two ones per ignited row (mask already zeroed by K1)
    if (tid < CHUNK) {
        unsigned i1 = sidx[tid * 2 + 0];
        if (i1 != 0xffffffffu) {
            unsigned i2 = sidx[tid * 2 + 1];
            size_t ro = (size_t)(c * CHUNK + tid) * (size_t)N;
            out_mask[ro + i1] = 1.0f;
            out_mask[ro + i2] = 1.0f;
        }
    }
}

// ---------------------------------------------------------------- launch
extern "C" void kernel_launch(void* const* d_in, const int* in_sizes, int n_in,
                              void* d_out, int out_size)
{
    const float* spikes = (const float*)d_in[0];
    const float* nmda0  = (const float*)d_in[1];
    int N = in_sizes[1];
    long long total = in_sizes[0];
    int T = (int)(total / N);

    float* out      = (float*)d_out;
    float* out_cov  = out + (size_t)T * N;
    float* out_nmda = out_cov + T;

    k_bitpack<<<2368, 256>>>(spikes, out, total);
    k_scan<<<N / 128, 128>>>(nmda0, out_nmda, T, N / 32);
    k_topk<<<T / CHUNK, 256>>>(out, out_cov, N);
}

// round 5
// speedup vs baseline: 2.3995x; 2.3995x over previous
#include <cuda_runtime.h>
#include <cstdint>

// GlobalWorkspace: exact EMA scan + per-step threshold/top-2 + mask scatter.
//
//   K1 k_pack      : read spikes (128MiB), ballot-pack to TRANSPOSED bit
//                    array g_bitsT[word][t] (4MiB).
//   K2 k_scan_zero : warp 0 scans 32 neurons bit-exactly from a contiguous
//                    smem bit column (cp.async); warps 1-3 zero-fill the
//                    128MiB ignite_mask concurrently. Emits 32-step carries.
//   K3 k_topk      : per 32-step chunk, replay EMA from exact carry, exact
//                    top-2 (u64 keys: score bits + ~idx tie-break) + raw max
//                    via __reduce_max_sync; write coverage + two 1.0s/row.
//
// XLA contracts (0.99*v + 0.01*s) into fma(0.99, v, 0.01*s); 0.01*s is exact
// for s in {0,1}. __fmaf_rn replicates it so all discrete decisions bit-match.

#define EMA_MUL 0.99f
#define EMA_ADD 0.01f
#define WTA     0.85f
#define THR     0.58f

#define MAX_T 8192
#define MAX_N 4096
#define CHUNK 32

// scratch (static __device__ — no allocations allowed)
static __device__ unsigned g_bitsT[(size_t)(MAX_N / 32) * MAX_T];         // 4 MiB, [word][t]
static __device__ float    g_carry[(size_t)(MAX_T / CHUNK) * MAX_N];      // 4 MiB

// ---------------------------------------------------------------- K1
// warp handles 128 consecutive elems/iter: lane loads 4 strided floats so
// each ballot is directly one output bit-word.
__global__ void k_pack(const float* __restrict__ spikes, long long total,
                       int lgN, int T)
{
    const int lane = threadIdx.x & 31;
    const long long warpsTotal = (long long)gridDim.x * (blockDim.x >> 5);
    const long long wid = (long long)blockIdx.x * (blockDim.x >> 5) + (threadIdx.x >> 5);
    const long long ngroups = total >> 7;            // 128 elems per group
    const unsigned nmask = (1u << lgN) - 1u;

    for (long long g = wid; g < ngroups; g += warpsTotal) {
        long long base = g << 7;
        const float* p = spikes + base + lane;
        float s0 = p[0], s1 = p[32], s2 = p[64], s3 = p[96];
        unsigned b0 = __ballot_sync(0xffffffffu, s0 != 0.0f);
        unsigned b1 = __ballot_sync(0xffffffffu, s1 != 0.0f);
        unsigned b2 = __ballot_sync(0xffffffffu, s2 != 0.0f);
        unsigned b3 = __ballot_sync(0xffffffffu, s3 != 0.0f);
        if (lane < 4) {
            unsigned w = (lane == 0) ? b0 : (lane == 1) ? b1 : (lane == 2) ? b2 : b3;
            long long t = base >> lgN;
            unsigned n0 = (unsigned)base & nmask;
            unsigned wi = (n0 >> 5) + (unsigned)lane;
            g_bitsT[(size_t)wi * T + t] = w;
        }
    }
}

// ---------------------------------------------------------------- K2
// grid = N/32 blocks, 128 threads. Block b owns bit-word column b.
__global__ __launch_bounds__(128) void k_scan_zero(const float* __restrict__ nmda0,
                                                   float* __restrict__ nmda_final,
                                                   float4* __restrict__ mask_zero,
                                                   int T, int N)
{
    __shared__ unsigned scol[MAX_T];                 // 32 KB bit column
    const int tid = threadIdx.x;
    const int wq  = blockIdx.x;

    // cp.async the whole contiguous column (T words = 32 KB) into smem
    {
        const unsigned* src = g_bitsT + (size_t)wq * T;
        int nchunks = T / 4;                         // 16B chunks
        for (int idx = tid; idx < nchunks; idx += blockDim.x) {
            unsigned sa = (unsigned)__cvta_generic_to_shared(&scol[idx * 4]);
            asm volatile("cp.async.cg.shared.global [%0], [%1], 16;"
                         :: "r"(sa), "l"(src + idx * 4));
        }
        asm volatile("cp.async.commit_group;\n\tcp.async.wait_group 0;" ::: "memory");
    }
    __syncthreads();

    if (tid < 32) {
        // ---- scan warp: 32 neurons, serial bit-exact chain
        const int lane = tid;
        const int n = wq * 32 + lane;
        const unsigned bitm = 1u << lane;
        float v = nmda0[n];
        const int nb = T / CHUNK;

        unsigned wa[CHUNK], wb[CHUNK];
        #pragma unroll
        for (int i = 0; i < CHUNK; i++) wa[i] = scol[i];

        for (int b = 0; b < nb; b += 2) {
            g_carry[(size_t)b * N + n] = v;
            #pragma unroll
            for (int i = 0; i < CHUNK; i++) wb[i] = scol[(b + 1) * CHUNK + i];
            #pragma unroll
            for (int i = 0; i < CHUNK; i++) {
                float a = (wa[i] & bitm) ? EMA_ADD : 0.0f;
                v = __fmaf_rn(EMA_MUL, v, a);
            }
            g_carry[(size_t)(b + 1) * N + n] = v;
            if (b + 2 < nb) {
                #pragma unroll
                for (int i = 0; i < CHUNK; i++) wa[i] = scol[(b + 2) * CHUNK + i];
            }
            #pragma unroll
            for (int i = 0; i < CHUNK; i++) {
                float a = (wb[i] & bitm) ? EMA_ADD : 0.0f;
                v = __fmaf_rn(EMA_MUL, v, a);
            }
        }
        nmda_final[n] = v;
    } else {
        // ---- zero-fill warps: 96 threads/block over the whole mask
        long long nv = ((long long)T * N) >> 2;      // float4 count
        long long zt = (long long)blockIdx.x * 96 + (tid - 32);
        long long zn = 96LL * gridDim.x;
        float4 z = make_float4(0.f, 0.f, 0.f, 0.f);
        for (long long i = zt; i < nv; i += zn) mask_zero[i] = z;
    }
}

// ---------------------------------------------------------------- K3
__device__ __forceinline__ void top2_merge(unsigned long long& m1, unsigned long long& m2,
                                           unsigned long long o1, unsigned long long o2)
{
    bool g = m1 > o1;
    unsigned long long hi = g ? m1 : o1;
    unsigned long long lo = g ? o1 : m1;
    unsigned long long s2 = (m2 > o2) ? m2 : o2;
    m1 = hi;
    m2 = (lo > s2) ? lo : s2;
}

// 256 threads, 16 neurons/thread (N=4096). blockIdx = chunk (32 steps).
__global__ __launch_bounds__(256) void k_topk(float* __restrict__ out_mask,
                                              float* __restrict__ out_cov,
                                              int N, int T)
{
    __shared__ unsigned sbits[128 * 33];             // padded [wq][t] tile
    __shared__ unsigned long long sm1[CHUNK * 8];
    __shared__ unsigned long long sm2[CHUNK * 8];
    __shared__ float smax[CHUNK * 8];
    __shared__ unsigned sidx[CHUNK * 2];

    const int tid = threadIdx.x;
    const int c   = blockIdx.x;
    const int w   = tid >> 5, lane = tid & 31;
    const int NW  = N >> 5;                          // 128

    // load bit tile from transposed layout (coalesced: warp = one column seg)
    for (int j = tid; j < NW * CHUNK; j += 256) {
        int wq = j >> 5, tt = j & 31;
        sbits[wq * 33 + tt] = g_bitsT[(size_t)wq * T + c * CHUNK + tt];
    }

    // load exact carry for my 16 neurons
    const int base = tid * 16;
    float ema[16];
    {
        const float4* cr = (const float4*)(g_carry + (size_t)c * N + base);
        #pragma unroll
        for (int q = 0; q < 4; q++) {
            float4 f = cr[q];
            ema[q * 4 + 0] = f.x; ema[q * 4 + 1] = f.y;
            ema[q * 4 + 2] = f.z; ema[q * 4 + 3] = f.w;
        }
    }
    __syncthreads();

    const unsigned invb = ~(unsigned)base;           // ~(base+j) = invb - j

    for (int t = 0; t < CHUNK; t++) {
        unsigned word = sbits[(tid >> 1) * 33 + t];
        unsigned half = word >> ((tid & 1) << 4);

        #pragma unroll
        for (int j = 0; j < 16; j++) {
            float a = ((half >> j) & 1u) ? EMA_ADD : 0.0f;
            ema[j] = __fmaf_rn(EMA_MUL, ema[j], a);  // identical to K2's update
        }

        // raw max via u32-monotone reduce (all ema >= 0)
        float rloc = ema[0];
        #pragma unroll
        for (int j = 1; j < 16; j++) rloc = fmaxf(rloc, ema[j]);
        unsigned rbits = __reduce_max_sync(0xffffffffu, __float_as_uint(rloc));

        // keys: (score_bits << 32) | ~idx
        unsigned long long key[16];
        #pragma unroll
        for (int j = 0; j < 16; j++) {
            unsigned sb = __float_as_uint(__fmul_rn(ema[j], WTA));
            key[j] = ((unsigned long long)sb << 32) | (unsigned long long)(invb - j);
        }

        unsigned long long p1[8], p2[8];
        #pragma unroll
        for (int p = 0; p < 8; p++) {
            unsigned long long ka = key[2 * p], kb = key[2 * p + 1];
            bool g = ka > kb;
            p1[p] = g ? ka : kb;
            p2[p] = g ? kb : ka;
        }
        #pragma unroll
        for (int s = 1; s < 8; s <<= 1)
            #pragma unroll
            for (int p = 0; p < 8; p += 2 * s)
                top2_merge(p1[p], p2[p], p1[p + s], p2[p + s]);

        unsigned long long m1 = p1[0], m2 = p2[0];
        #pragma unroll
        for (int d = 16; d >= 1; d >>= 1) {
            unsigned long long o1 = __shfl_xor_sync(0xffffffffu, m1, d);
            unsigned long long o2 = __shfl_xor_sync(0xffffffffu, m2, d);
            top2_merge(m1, m2, o1, o2);
        }
        if (lane == 0) {
            sm1[t * 8 + w] = m1; sm2[t * 8 + w] = m2;
            smax[t * 8 + w] = __uint_as_float(rbits);
        }
    }
    __syncthreads();

    // cross-warp reduce (8 entries per step), finalize per step
    const float covval = __fdiv_rn(2.0f, (float)N);
    for (int t = w; t < CHUNK; t += 8) {
        unsigned long long m1 = 0ull, m2 = 0ull;
        float rmx = 0.0f;
        if (lane < 8) { m1 = sm1[t * 8 + lane]; m2 = sm2[t * 8 + lane]; rmx = smax[t * 8 + lane]; }
        #pragma unroll
        for (int d = 4; d >= 1; d >>= 1) {
            unsigned long long o1 = __shfl_xor_sync(0xffffffffu, m1, d);
            unsigned long long o2 = __shfl_xor_sync(0xffffffffu, m2, d);
            float om            = __shfl_xor_sync(0xffffffffu, rmx, d);
            top2_merge(m1, m2, o1, o2);
            rmx = fmaxf(rmx, om);
        }
        if (lane == 0) {
            bool ign = (rmx >= THR);
            out_cov[c * CHUNK + t] = ign ? covval : 0.0f;
            sidx[t * 2 + 0] = ign ? ~(unsigned)(m1 & 0xffffffffull) : 0xffffffffu;
            sidx[t * 2 + 1] = ign ? ~(unsigned)(m2 & 0xffffffffull) : 0xffffffffu;
        }
    }
    __syncthreads();

    // scatter the two ones per ignited row (mask zeroed by K2)
    if (tid < CHUNK) {
        unsigned i1 = sidx[tid * 2 + 0];
        if (i1 != 0xffffffffu) {
            unsigned i2 = sidx[tid * 2 + 1];
            size_t ro = (size_t)(c * CHUNK + tid) * (size_t)N;
            out_mask[ro + i1] = 1.0f;
            out_mask[ro + i2] = 1.0f;
        }
    }
}

// ---------------------------------------------------------------- launch
extern "C" void kernel_launch(void* const* d_in, const int* in_sizes, int n_in,
                              void* d_out, int out_size)
{
    const float* spikes = (const float*)d_in[0];
    const float* nmda0  = (const float*)d_in[1];
    int N = in_sizes[1];
    long long total = in_sizes[0];
    int T = (int)(total / N);

    int lgN = 0; while ((1 << lgN) < N) lgN++;

    float* out      = (float*)d_out;
    float* out_cov  = out + (size_t)T * N;
    float* out_nmda = out_cov + T;

    k_pack<<<2368, 256>>>(spikes, total, lgN, T);
    k_scan_zero<<<N / 32, 128>>>(nmda0, out_nmda, (float4*)out, T, N);
    k_topk<<<T / CHUNK, 256>>>(out, out_cov, N, T);
}

// round 8
// speedup vs baseline: 2.5209x; 1.0506x over previous
#include <cuda_runtime.h>
#include <cstdint>

// GlobalWorkspace: exact EMA scan + per-step threshold/top-2 + mask scatter.
//
//   K1 k_pack      : read spikes (128MiB) as float4, shfl-OR pack to
//                    TRANSPOSED bit array g_bitsT[word][t] (4MiB).
//   K2 k_scan_zero : 148 blocks. Blocks <128: warp 0 scans 32 neurons
//                    bit-exactly from a contiguous smem bit column
//                    (cp.async); warps 1-7 zero-fill the mask. Blocks >=128:
//                    pure fill. Emits 32-step carries.
//   K3 k_topk      : per 32-step chunk, replay EMA from exact carry; per
//                    thread sequential u32 top-2 scan (16 neurons), u64
//                    (score,~idx) butterfly across warp, raw max via
//                    __reduce_max_sync; coverage + two 1.0 stores per row.
//
// XLA contracts (0.99*v + 0.01*s) into fma(0.99, v, 0.01*s); 0.01*s is exact
// for s in {0,1}. __fmaf_rn replicates it so all discrete decisions bit-match.

#define EMA_MUL 0.99f
#define EMA_ADD 0.01f
#define WTA     0.85f
#define THR     0.58f

#define MAX_T 8192
#define MAX_N 4096
#define CHUNK 32

// scratch (static __device__ — no allocations allowed)
static __device__ unsigned g_bitsT[(size_t)(MAX_N / 32) * MAX_T];         // 4 MiB, [word][t]
static __device__ float    g_carry[(size_t)(MAX_T / CHUNK) * MAX_N];      // 4 MiB

// ---------------------------------------------------------------- K1
// lane loads one float4; warp covers 128 consecutive floats. 4 bits/lane,
// OR-combined within 8-lane groups via 3 shfl-xor; group leaders store.
__global__ void k_pack(const float4* __restrict__ sp4, long long ngroups,
                       int lgN, int T)
{
    const int lane = threadIdx.x & 31;
    const long long wtot = (long long)gridDim.x * (blockDim.x >> 5);
    long long wid = (long long)blockIdx.x * (blockDim.x >> 5) + (threadIdx.x >> 5);
    const unsigned nmask = (1u << lgN) - 1u;

    for (long long g = wid; g < ngroups; g += wtot) {
        float4 v4 = sp4[(g << 5) + lane];
        unsigned nib = (v4.x != 0.0f ? 1u : 0u) | (v4.y != 0.0f ? 2u : 0u)
                     | (v4.z != 0.0f ? 4u : 0u) | (v4.w != 0.0f ? 8u : 0u);
        unsigned v = nib << ((lane & 7) * 4);
        v |= __shfl_xor_sync(0xffffffffu, v, 1);
        v |= __shfl_xor_sync(0xffffffffu, v, 2);
        v |= __shfl_xor_sync(0xffffffffu, v, 4);
        if ((lane & 7) == 0) {
            long long base = g << 7;
            long long t = base >> lgN;
            unsigned n0 = (unsigned)base & nmask;
            unsigned wi = (n0 >> 5) + (unsigned)(lane >> 3);
            g_bitsT[(size_t)wi * T + t] = v;
        }
    }
}

// ---------------------------------------------------------------- K2
// 148 blocks x 256 threads. Blocks 0..127: scan warp + 224 fill threads.
// Blocks 128..147: 256 fill threads.
__global__ __launch_bounds__(256) void k_scan_zero(const float* __restrict__ nmda0,
                                                   float* __restrict__ nmda_final,
                                                   float4* __restrict__ mask_zero,
                                                   int T, int N, int nScanBlocks,
                                                   int nExtra)
{
    __shared__ unsigned scol[MAX_T];                 // 32 KB bit column
    const int tid = threadIdx.x;
    const int b   = blockIdx.x;
    const bool isScanBlock = (b < nScanBlocks);

    if (isScanBlock) {
        // cp.async the whole contiguous column (T words = 32 KB) into smem
        const unsigned* src = g_bitsT + (size_t)b * T;
        int nchunks = T / 4;                         // 16B chunks
        for (int idx = tid; idx < nchunks; idx += blockDim.x) {
            unsigned sa = (unsigned)__cvta_generic_to_shared(&scol[idx * 4]);
            asm volatile("cp.async.cg.shared.global [%0], [%1], 16;"
                         :: "r"(sa), "l"(src + idx * 4));
        }
        asm volatile("cp.async.commit_group;\n\tcp.async.wait_group 0;" ::: "memory");
        __syncthreads();
    }

    if (isScanBlock && tid < 32) {
        // ---- scan warp: 32 neurons, serial bit-exact chain
        const int lane = tid;
        const int n = b * 32 + lane;
        const unsigned bitm = 1u << lane;
        float v = nmda0[n];
        const int nb = T / CHUNK;

        unsigned wa[CHUNK], wb[CHUNK];
        #pragma unroll
        for (int i = 0; i < CHUNK; i++) wa[i] = scol[i];

        for (int bb = 0; bb < nb; bb += 2) {
            g_carry[(size_t)bb * N + n] = v;
            #pragma unroll
            for (int i = 0; i < CHUNK; i++) wb[i] = scol[(bb + 1) * CHUNK + i];
            #pragma unroll
            for (int i = 0; i < CHUNK; i++) {
                float a = (wa[i] & bitm) ? EMA_ADD : 0.0f;
                v = __fmaf_rn(EMA_MUL, v, a);
            }
            g_carry[(size_t)(bb + 1) * N + n] = v;
            if (bb + 2 < nb) {
                #pragma unroll
                for (int i = 0; i < CHUNK; i++) wa[i] = scol[(bb + 2) * CHUNK + i];
            }
            #pragma unroll
            for (int i = 0; i < CHUNK; i++) {
                float a = (wb[i] & bitm) ? EMA_ADD : 0.0f;
                v = __fmaf_rn(EMA_MUL, v, a);
            }
        }
        nmda_final[n] = v;
    } else {
        // ---- fill threads: scan blocks contribute 224, extra blocks 256
        long long fid, nf = (long long)nScanBlocks * 224 + (long long)nExtra * 256;
        if (isScanBlock) fid = (long long)b * 224 + (tid - 32);
        else             fid = (long long)nScanBlocks * 224 + (long long)(b - nScanBlocks) * 256 + tid;

        long long nv = ((long long)T * N) >> 2;      // float4 count
        float4 z = make_float4(0.f, 0.f, 0.f, 0.f);
        for (long long i = fid; i < nv; i += nf) mask_zero[i] = z;
    }
}

// ---------------------------------------------------------------- K3
__device__ __forceinline__ void top2_merge(unsigned long long& m1, unsigned long long& m2,
                                           unsigned long long o1, unsigned long long o2)
{
    bool g = m1 > o1;
    unsigned long long hi = g ? m1 : o1;
    unsigned long long lo = g ? o1 : m1;
    unsigned long long s2 = (m2 > o2) ? m2 : o2;
    m1 = hi;
    m2 = (lo > s2) ? lo : s2;
}

// 256 threads, 16 neurons/thread (N=4096). blockIdx = chunk (32 steps).
__global__ __launch_bounds__(256) void k_topk(float* __restrict__ out_mask,
                                              float* __restrict__ out_cov,
                                              int N, int T)
{
    __shared__ unsigned sbits[128 * 33];             // padded [wq][t] tile
    __shared__ unsigned long long sm1[CHUNK * 8];
    __shared__ unsigned long long sm2[CHUNK * 8];
    __shared__ float smax[CHUNK * 8];
    __shared__ unsigned sidx[CHUNK * 2];

    const int tid = threadIdx.x;
    const int c   = blockIdx.x;
    const int w   = tid >> 5, lane = tid & 31;
    const int NW  = N >> 5;                          // 128

    // load bit tile from transposed layout (coalesced: warp = one column seg)
    for (int j = tid; j < NW * CHUNK; j += 256) {
        int wq = j >> 5, tt = j & 31;
        sbits[wq * 33 + tt] = g_bitsT[(size_t)wq * T + c * CHUNK + tt];
    }

    // load exact carry for my 16 neurons
    const int base = tid * 16;
    float ema[16];
    {
        const float4* cr = (const float4*)(g_carry + (size_t)c * N + base);
        #pragma unroll
        for (int q = 0; q < 4; q++) {
            float4 f = cr[q];
            ema[q * 4 + 0] = f.x; ema[q * 4 + 1] = f.y;
            ema[q * 4 + 2] = f.z; ema[q * 4 + 3] = f.w;
        }
    }
    __syncthreads();

    const unsigned invb = ~(unsigned)base;           // ~(base+j) = invb - j

    for (int t = 0; t < CHUNK; t++) {
        unsigned word = sbits[(tid >> 1) * 33 + t];
        unsigned half = word >> ((tid & 1) << 4);

        // fused: EMA update + raw max + sequential u32 top-2 scan.
        // strict '>' keeps the earlier index on ties (jax top_k semantics);
        // indices tracked pre-complemented (iv = ~(base+j)).
        unsigned b1 = 0u, i1 = 0xffffffffu, b2 = 0u, i2 = 0xffffffffu;
        float rloc = 0.0f;
        #pragma unroll
        for (int j = 0; j < 16; j++) {
            float a = ((half >> j) & 1u) ? EMA_ADD : 0.0f;
            float e = __fmaf_rn(EMA_MUL, ema[j], a); // identical to K2's update
            ema[j] = e;
            rloc = fmaxf(rloc, e);
            unsigned sb = __float_as_uint(__fmul_rn(e, WTA));
            unsigned iv = invb - j;
            bool p1 = sb > b1;
            bool p2 = sb > b2;
            b2 = p1 ? b1 : (p2 ? sb : b2);
            i2 = p1 ? i1 : (p2 ? iv : i2);
            b1 = p1 ? sb : b1;
            i1 = p1 ? iv : i1;
        }
        unsigned rbits = __reduce_max_sync(0xffffffffu, __float_as_uint(rloc));

        unsigned long long m1 = ((unsigned long long)b1 << 32) | i1;
        unsigned long long m2 = ((unsigned long long)b2 << 32) | i2;
        #pragma unroll
        for (int d = 16; d >= 1; d >>= 1) {
            unsigned long long o1 = __shfl_xor_sync(0xffffffffu, m1, d);
            unsigned long long o2 = __shfl_xor_sync(0xffffffffu, m2, d);
            top2_merge(m1, m2, o1, o2);
        }
        if (lane == 0) {
            sm1[t * 8 + w] = m1; sm2[t * 8 + w] = m2;
            smax[t * 8 + w] = __uint_as_float(rbits);
        }
    }
    __syncthreads();

    // cross-warp reduce (8 entries per step), finalize per step
    const float covval = __fdiv_rn(2.0f, (float)N);
    for (int t = w; t < CHUNK; t += 8) {
        unsigned long long m1 = 0ull, m2 = 0ull;
        float rmx = 0.0f;
        if (lane < 8) { m1 = sm1[t * 8 + lane]; m2 = sm2[t * 8 + lane]; rmx = smax[t * 8 + lane]; }
        #pragma unroll
        for (int d = 4; d >= 1; d >>= 1) {
            unsigned long long o1 = __shfl_xor_sync(0xffffffffu, m1, d);
            unsigned long long o2 = __shfl_xor_sync(0xffffffffu, m2, d);
            float om            = __shfl_xor_sync(0xffffffffu, rmx, d);
            top2_merge(m1, m2, o1, o2);
            rmx = fmaxf(rmx, om);
        }
        if (lane == 0) {
            bool ign = (rmx >= THR);
            out_cov[c * CHUNK + t] = ign ? covval : 0.0f;
            sidx[t * 2 + 0] = ign ? ~(unsigned)(m1 & 0xffffffffull) : 0xffffffffu;
            sidx[t * 2 + 1] = ign ? ~(unsigned)(m2 & 0xffffffffull) : 0xffffffffu;
        }
    }
    __syncthreads();

    // scatter the two ones per ignited row (mask zeroed by K2)
    if (tid < CHUNK) {
        unsigned i1s = sidx[tid * 2 + 0];
        if (i1s != 0xffffffffu) {
            unsigned i2s = sidx[tid * 2 + 1];
            size_t ro = (size_t)(c * CHUNK + tid) * (size_t)N;
            out_mask[ro + i1s] = 1.0f;
            out_mask[ro + i2s] = 1.0f;
        }
    }
}

// ---------------------------------------------------------------- launch
extern "C" void kernel_launch(void* const* d_in, const int* in_sizes, int n_in,
                              void* d_out, int out_size)
{
    const float* spikes = (const float*)d_in[0];
    const float* nmda0  = (const float*)d_in[1];
    int N = in_sizes[1];
    long long total = in_sizes[0];
    int T = (int)(total / N);

    int lgN = 0; while ((1 << lgN) < N) lgN++;

    float* out      = (float*)d_out;
    float* out_cov  = out + (size_t)T * N;
    float* out_nmda = out_cov + T;

    int nScanBlocks = N / 32;                        // 128
    int nExtra = 20;                                 // pure-fill blocks

    k_pack<<<2368, 256>>>((const float4*)spikes, total >> 7, lgN, T);
    k_scan_zero<<<nScanBlocks + nExtra, 256>>>(nmda0, out_nmda, (float4*)out,
                                               T, N, nScanBlocks, nExtra);
    k_topk<<<T / CHUNK, 256>>>(out, out_cov, N, T);
}

// round 11
// speedup vs baseline: 2.8209x; 1.1190x over previous
#include <cuda_runtime.h>
#include <cstdint>

// GlobalWorkspace: exact EMA scan + per-step threshold/top-2 + mask rows.
//
//   K1 k_pack : read spikes (128MiB) as 2x float4/lane, shfl-OR pack to
//               TRANSPOSED bit array g_bitsT[word][t] (4MiB).
//   K2 k_scan : scan-only. 128 blocks x 128 thr; cp.async one contiguous
//               32KB bit column to smem; warp 0 runs the bit-exact serial
//               EMA for 32 neurons, emitting 32-step carries + nmda_final.
//   K3 k_topk : per 32-step chunk: zero-stream the 32 output rows (512KB),
//               replay EMA from exact carry, REDUX-based exact top-2
//               (score bits + ~idx tie-break) + raw max, then scatter the
//               two 1.0 entries per ignited row + coverage.
//
// XLA contracts (0.99*v + 0.01*s) into fma(0.99, v, 0.01*s); 0.01*s is exact
// for s in {0,1}. __fmaf_rn replicates it so all discrete decisions bit-match.

#define EMA_MUL 0.99f
#define EMA_ADD 0.01f
#define WTA     0.85f
#define THR     0.58f

#define MAX_T 8192
#define MAX_N 4096
#define CHUNK 32

// scratch (static __device__ — no allocations allowed)
static __device__ unsigned g_bitsT[(size_t)(MAX_N / 32) * MAX_T];         // 4 MiB, [word][t]
static __device__ float    g_carry[(size_t)(MAX_T / CHUNK) * MAX_N];      // 4 MiB

// ---------------------------------------------------------------- K1
// warp iter covers 256 consecutive floats: 2 independent float4 loads/lane.
__device__ __forceinline__ unsigned nib4(float4 v)
{
    return (v.x != 0.0f ? 1u : 0u) | (v.y != 0.0f ? 2u : 0u)
         | (v.z != 0.0f ? 4u : 0u) | (v.w != 0.0f ? 8u : 0u);
}

__global__ void k_pack(const float4* __restrict__ sp4, long long niter,
                       int lgN, int T)
{
    const int lane = threadIdx.x & 31;
    const long long wtot = (long long)gridDim.x * (blockDim.x >> 5);
    long long wid = (long long)blockIdx.x * (blockDim.x >> 5) + (threadIdx.x >> 5);
    const unsigned nmask = (1u << lgN) - 1u;
    const int sh = (lane & 7) * 4;

    for (long long g = wid; g < niter; g += wtot) {
        const float4* p = sp4 + (g << 6);
        float4 fa = p[lane];
        float4 fb = p[lane + 32];
        unsigned va = nib4(fa) << sh;
        unsigned vb = nib4(fb) << sh;
        va |= __shfl_xor_sync(0xffffffffu, va, 1);
        vb |= __shfl_xor_sync(0xffffffffu, vb, 1);
        va |= __shfl_xor_sync(0xffffffffu, va, 2);
        vb |= __shfl_xor_sync(0xffffffffu, vb, 2);
        va |= __shfl_xor_sync(0xffffffffu, va, 4);
        vb |= __shfl_xor_sync(0xffffffffu, vb, 4);
        if ((lane & 7) == 0) {
            long long base = g << 8;              // first float of this group
            long long t = base >> lgN;
            unsigned n0 = (unsigned)base & nmask;
            unsigned wi = (n0 >> 5) + (unsigned)(lane >> 3);
            g_bitsT[(size_t)wi * T + t] = va;     // words wi..wi+3 (floats +0..127)
            g_bitsT[(size_t)(wi + 4) * T + t] = vb; // words +4..+7 (floats +128..255)
        }
    }
}

// ---------------------------------------------------------------- K2
// grid = N/32 blocks x 128 threads. Block b owns bit-word column b.
__global__ __launch_bounds__(128) void k_scan(const float* __restrict__ nmda0,
                                              float* __restrict__ nmda_final,
                                              int T, int N)
{
    __shared__ unsigned scol[MAX_T];                 // 32 KB bit column
    const int tid = threadIdx.x;
    const int b   = blockIdx.x;

    // cp.async the whole contiguous column (T words = 32 KB) into smem
    {
        const unsigned* src = g_bitsT + (size_t)b * T;
        int nchunks = T / 4;                         // 16B chunks
        for (int idx = tid; idx < nchunks; idx += blockDim.x) {
            unsigned sa = (unsigned)__cvta_generic_to_shared(&scol[idx * 4]);
            asm volatile("cp.async.cg.shared.global [%0], [%1], 16;"
                         :: "r"(sa), "l"(src + idx * 4));
        }
        asm volatile("cp.async.commit_group;\n\tcp.async.wait_group 0;" ::: "memory");
    }
    __syncthreads();
    if (tid >= 32) return;

    // ---- scan warp: 32 neurons, serial bit-exact chain
    const int lane = tid;
    const int n = b * 32 + lane;
    const unsigned bitm = 1u << lane;
    float v = nmda0[n];
    const int nb = T / CHUNK;

    unsigned wa[CHUNK], wb[CHUNK];
    #pragma unroll
    for (int i = 0; i < CHUNK; i++) wa[i] = scol[i];

    for (int bb = 0; bb < nb; bb += 2) {
        g_carry[(size_t)bb * N + n] = v;
        #pragma unroll
        for (int i = 0; i < CHUNK; i++) wb[i] = scol[(bb + 1) * CHUNK + i];
        #pragma unroll
        for (int i = 0; i < CHUNK; i++) {
            float a = (wa[i] & bitm) ? EMA_ADD : 0.0f;
            v = __fmaf_rn(EMA_MUL, v, a);
        }
        g_carry[(size_t)(bb + 1) * N + n] = v;
        if (bb + 2 < nb) {
            #pragma unroll
            for (int i = 0; i < CHUNK; i++) wa[i] = scol[(bb + 2) * CHUNK + i];
        }
        #pragma unroll
        for (int i = 0; i < CHUNK; i++) {
            float a = (wb[i] & bitm) ? EMA_ADD : 0.0f;
            v = __fmaf_rn(EMA_MUL, v, a);
        }
    }
    nmda_final[n] = v;
}

// ---------------------------------------------------------------- K3
__device__ __forceinline__ void top2_merge(unsigned long long& m1, unsigned long long& m2,
                                           unsigned long long o1, unsigned long long o2)
{
    bool g = m1 > o1;
    unsigned long long hi = g ? m1 : o1;
    unsigned long long lo = g ? o1 : m1;
    unsigned long long s2 = (m2 > o2) ? m2 : o2;
    m1 = hi;
    m2 = (lo > s2) ? lo : s2;
}

// 256 threads, 16 neurons/thread (N=4096). blockIdx = chunk (32 steps).
__global__ __launch_bounds__(256) void k_topk(float* __restrict__ out_mask,
                                              float* __restrict__ out_cov,
                                              int N, int T)
{
    __shared__ unsigned sbits[128 * 33];             // padded [wq][t] tile
    __shared__ unsigned long long sm1[CHUNK * 8];
    __shared__ unsigned long long sm2[CHUNK * 8];
    __shared__ float smax[CHUNK * 8];
    __shared__ unsigned sidx[CHUNK * 2];

    const int tid = threadIdx.x;
    const int c   = blockIdx.x;
    const int w   = tid >> 5, lane = tid & 31;
    const int NW  = N >> 5;                          // 128

    // load bit tile from transposed layout (coalesced: warp = one column seg)
    for (int j = tid; j < NW * CHUNK; j += 256) {
        int wq = j >> 5, tt = j & 31;
        sbits[wq * 33 + tt] = g_bitsT[(size_t)wq * T + c * CHUNK + tt];
    }

    // load exact carry for my 16 neurons
    const int base = tid * 16;
    float ema[16];
    {
        const float4* cr = (const float4*)(g_carry + (size_t)c * N + base);
        #pragma unroll
        for (int q = 0; q < 4; q++) {
            float4 f = cr[q];
            ema[q * 4 + 0] = f.x; ema[q * 4 + 1] = f.y;
            ema[q * 4 + 2] = f.z; ema[q * 4 + 3] = f.w;
        }
    }
    __syncthreads();

    // ---- D1: stream zeros over this block's 32 output rows (512 KB).
    // Independent of the compute; stores drain while phase A runs.
    {
        float4* out4 = (float4*)(out_mask + (size_t)c * CHUNK * N);
        const int nv = CHUNK * (N >> 2);             // 32768 float4
        float4 z = make_float4(0.f, 0.f, 0.f, 0.f);
        for (int i = tid; i < nv; i += 256) out4[i] = z;
    }

    const unsigned invb = ~(unsigned)base;           // ~(base+j) = invb - j

    // ---- phase A: replay 32 steps; per-thread seq top-2; REDUX warp merge
    for (int t = 0; t < CHUNK; t++) {
        unsigned word = sbits[(tid >> 1) * 33 + t];
        unsigned half = word >> ((tid & 1) << 4);

        unsigned b1 = 0u, i1 = 0xffffffffu, b2 = 0u, i2 = 0xffffffffu;
        float rloc = 0.0f;
        #pragma unroll
        for (int j = 0; j < 16; j++) {
            float a = ((half >> j) & 1u) ? EMA_ADD : 0.0f;
            float e = __fmaf_rn(EMA_MUL, ema[j], a); // identical to K2's update
            ema[j] = e;
            rloc = fmaxf(rloc, e);
            unsigned sb = __float_as_uint(__fmul_rn(e, WTA));
            unsigned iv = invb - j;
            bool p1 = sb > b1;
            bool p2 = sb > b2;
            b2 = p1 ? b1 : (p2 ? sb : b2);
            i2 = p1 ? i1 : (p2 ? iv : i2);
            b1 = p1 ? sb : b1;
            i1 = p1 ? iv : i1;
        }
        unsigned rbits = __reduce_max_sync(0xffffffffu, __float_as_uint(rloc));

        // warp top-2 via REDUX: max score, owner (largest ~idx on ties),
        // then max over candidates with the owner's entry swapped for its 2nd.
        unsigned M1 = __reduce_max_sync(0xffffffffu, b1);
        unsigned I1 = __reduce_max_sync(0xffffffffu, (b1 == M1) ? i1 : 0u);
        bool own = (b1 == M1) && (i1 == I1);
        unsigned cb = own ? b2 : b1;
        unsigned ci = own ? i2 : i1;
        unsigned M2 = __reduce_max_sync(0xffffffffu, cb);
        unsigned I2 = __reduce_max_sync(0xffffffffu, (cb == M2) ? ci : 0u);

        if (lane == 0) {
            sm1[t * 8 + w] = ((unsigned long long)M1 << 32) | I1;
            sm2[t * 8 + w] = ((unsigned long long)M2 << 32) | I2;
            smax[t * 8 + w] = __uint_as_float(rbits);
        }
    }
    __syncthreads();

    // ---- phase B: cross-warp reduce (8 entries per step), finalize per step
    const float covval = __fdiv_rn(2.0f, (float)N);
    for (int t = w; t < CHUNK; t += 8) {
        unsigned long long m1 = 0ull, m2 = 0ull;
        float rmx = 0.0f;
        if (lane < 8) { m1 = sm1[t * 8 + lane]; m2 = sm2[t * 8 + lane]; rmx = smax[t * 8 + lane]; }
        #pragma unroll
        for (int d = 4; d >= 1; d >>= 1) {
            unsigned long long o1 = __shfl_xor_sync(0xffffffffu, m1, d);
            unsigned long long o2 = __shfl_xor_sync(0xffffffffu, m2, d);
            float om            = __shfl_xor_sync(0xffffffffu, rmx, d);
            top2_merge(m1, m2, o1, o2);
            rmx = fmaxf(rmx, om);
        }
        if (lane == 0) {
            bool ign = (rmx >= THR);
            out_cov[c * CHUNK + t] = ign ? covval : 0.0f;
            sidx[t * 2 + 0] = ign ? ~(unsigned)(m1 & 0xffffffffull) : 0xffffffffu;
            sidx[t * 2 + 1] = ign ? ~(unsigned)(m2 & 0xffffffffull) : 0xffffffffu;
        }
    }
    __syncthreads();   // orders D1 zero-stores + sidx before D2 ones

    // ---- D2: scatter the two ones per ignited row
    if (tid < CHUNK) {
        unsigned i1s = sidx[tid * 2 + 0];
        if (i1s != 0xffffffffu) {
            unsigned i2s = sidx[tid * 2 + 1];
            size_t ro = (size_t)(c * CHUNK + tid) * (size_t)N;
            out_mask[ro + i1s] = 1.0f;
            out_mask[ro + i2s] = 1.0f;
        }
    }
}

// ---------------------------------------------------------------- launch
extern "C" void kernel_launch(void* const* d_in, const int* in_sizes, int n_in,
                              void* d_out, int out_size)
{
    const float* spikes = (const float*)d_in[0];
    const float* nmda0  = (const float*)d_in[1];
    int N = in_sizes[1];
    long long total = in_sizes[0];
    int T = (int)(total / N);

    int lgN = 0; while ((1 << lgN) < N) lgN++;

    float* out      = (float*)d_out;
    float* out_cov  = out + (size_t)T * N;
    float* out_nmda = out_cov + T;

    k_pack<<<2368, 256>>>((const float4*)spikes, total >> 8, lgN, T);
    k_scan<<<N / 32, 128>>>(nmda0, out_nmda, T, N);
    k_topk<<<T / CHUNK, 256>>>(out, out_cov, N, T);
}